// round 7
// baseline (speedup 1.0000x reference)
#include <cuda_runtime.h>
#include <cuda_bf16.h>

// S4D live path == causal conv of u with K[h,m] = sum_n c[h,n] * r[h,n]^m,
// i.e. a bank of first-order IIR filters:  s_n[l] = u[l] + r_n*s_n[l-1],
// y[l] = sum_n c_n * s_n[l].  A prep kernel merges bitwise-identical poles
// per head (for the given inputs all 32 modes share one pole -> 1 scan pass).
// Main kernel: one CTA per (b,h) row, blocked Kogge-Stone scan of affine
// carry maps (x -> R*x + s), fully memory-bound streaming.

#define LROW  4096
#define TPB   256
#define SEG   16          // LROW / TPB
#define MAXH  512
#define MAXNH 32

__device__ float g_logr[MAXH * MAXNH];   // dtA (log of pole r) per compact pole
__device__ float g_coef[MAXH * MAXNH];   // merged coefficient per compact pole
__device__ int   g_cnt[MAXH];            // compact pole count per head

// ---------------------------------------------------------------------------
// Prep: per head, compute (dtA, c) for each mode, merge identical poles.
// ---------------------------------------------------------------------------
__global__ void s4d_prep_kernel(const float* __restrict__ C,
                                const float* __restrict__ log_dt,
                                const float* __restrict__ log_A_real,
                                int H, int NH) {
    int h = blockIdx.x * blockDim.x + threadIdx.x;
    if (h >= H) return;
    if (NH > MAXNH) NH = MAXNH;

    float dt = expf(log_dt[h]);
    float lr[MAXNH];
    float cc[MAXNH];
    int cnt = 0;
    for (int n = 0; n < NH; n++) {
        float A   = -expf(log_A_real[h * NH + n]);
        float dtA = A * dt;
        float c   = C[(h * NH + n) * 2] * (expf(dtA) - 1.0f) / A;
        int f = -1;
        for (int k = 0; k < cnt; k++)
            if (__float_as_int(lr[k]) == __float_as_int(dtA)) { f = k; break; }
        if (f >= 0) cc[f] += c;
        else { lr[cnt] = dtA; cc[cnt] = c; cnt++; }
    }
    for (int k = 0; k < cnt; k++) {
        g_logr[h * MAXNH + k] = lr[k];
        g_coef[h * MAXNH + k] = cc[k];
    }
    g_cnt[h] = cnt;
}

// ---------------------------------------------------------------------------
// Main: one CTA per (b,h) row.  256 threads x 16 contiguous elements each.
// Pass1: per-thread serial recurrence from 0.  Scan affine carries across
// threads (warp shuffle Kogge-Stone + 8-warp fixup).  Pass2: replay with
// incoming carry, accumulate y.  Shared padded stride-17 => conflict-free.
// ---------------------------------------------------------------------------
__global__ __launch_bounds__(TPB)
void s4d_scan_kernel(const float* __restrict__ u, float* __restrict__ y, int H) {
    __shared__ float sbuf[LROW + LROW / SEG];   // padded: phys = l + (l>>4)
    __shared__ float warpT[TPB / 32];

    const int bh   = blockIdx.x;
    const int h    = bh % H;
    const int tid  = threadIdx.x;
    const int lane = tid & 31;
    const int warp = tid >> 5;

    const float* __restrict__ urow = u + (size_t)bh * LROW;
    float* __restrict__       yrow = y + (size_t)bh * LROW;

    // Coalesced global -> padded shared (2-way worst-case bank pattern)
#pragma unroll
    for (int k = 0; k < LROW / TPB; k++) {
        int l = k * TPB + tid;
        sbuf[l + (l >> 4)] = urow[l];
    }
    __syncthreads();

    // Per-thread contiguous segment into registers (stride 17 -> conflict-free)
    float ur[SEG], yr[SEG];
    const int base = tid * (SEG + 1);
#pragma unroll
    for (int i = 0; i < SEG; i++) { ur[i] = sbuf[base + i]; yr[i] = 0.0f; }

    const int cnt = g_cnt[h];
    for (int p = 0; p < cnt; p++) {
        const float dtA = g_logr[h * MAXNH + p];
        const float c   = g_coef[h * MAXNH + p];
        const float r   = expf(dtA);

        // Pass 1: local recurrence from state 0
        float s = 0.0f;
#pragma unroll
        for (int i = 0; i < SEG; i++) s = fmaf(r, s, ur[i]);

        // Inclusive warp scan of carries under combine (x -> Rseg*x + s)
        float Rseg = expf(dtA * (float)SEG);   // r^SEG
        float v = s, pw = Rseg;
#pragma unroll
        for (int k = 1; k < 32; k <<= 1) {
            float t = __shfl_up_sync(0xffffffffu, v, k);
            if (lane >= k) v = fmaf(pw, t, v);
            pw *= pw;                           // Rseg^(2k)
        }
        if (lane == 31) warpT[warp] = v;
        __syncthreads();

        // Cross-warp prefix (<= 7 FMAs)
        const float Rwarp = expf(dtA * (float)(SEG * 32));  // r^(SEG*32)
        float J = 0.0f;
        for (int w = 0; w < warp; w++) J = fmaf(J, Rwarp, warpT[w]);
        __syncthreads();                        // warpT reused next pole

        // Exclusive carry for this thread's segment
        float E = __shfl_up_sync(0xffffffffu, v, 1);
        if (lane == 0) E = 0.0f;
        float carry = fmaf(J, expf(dtA * (float)(SEG * lane)), E);

        // Pass 2: replay with carry, accumulate output
        s = carry;
#pragma unroll
        for (int i = 0; i < SEG; i++) {
            s = fmaf(r, s, ur[i]);
            yr[i] = fmaf(c, s, yr[i]);
        }
    }
    __syncthreads();

    // Registers -> padded shared -> coalesced global store
#pragma unroll
    for (int i = 0; i < SEG; i++) sbuf[base + i] = yr[i];
    __syncthreads();
#pragma unroll
    for (int k = 0; k < LROW / TPB; k++) {
        int l = k * TPB + tid;
        yrow[l] = sbuf[l + (l >> 4)];
    }
}

// ---------------------------------------------------------------------------
extern "C" void kernel_launch(void* const* d_in, const int* in_sizes, int n_in,
                              void* d_out, int out_size) {
    const float* u           = (const float*)d_in[0];   // (B,H,L)
    const float* C           = (const float*)d_in[1];   // (H,N/2,2)
    const float* log_dt      = (const float*)d_in[2];   // (H,)
    const float* log_A_real  = (const float*)d_in[3];   // (H,N/2)
    float*       y           = (float*)d_out;

    const int H    = in_sizes[2];
    const int NH   = in_sizes[3] / H;
    const int rows = in_sizes[0] / LROW;                // B*H

    s4d_prep_kernel<<<(H + 255) / 256, 256>>>(C, log_dt, log_A_real, H, NH);
    s4d_scan_kernel<<<rows, TPB>>>(u, y, H);
}